// round 13
// baseline (speedup 1.0000x reference)
#include <cuda_runtime.h>
#include <cuda_fp16.h>

// ---------------------------------------------------------------------------
// BUIR / LightGCN forward, all-fp16 HFMA2 SpMM, bucketed CSR, half-warp rows.
//   - Online+target embeddings interleaved per node: H[r] = [64 on | 64 tg]
//     fp16 = 256B row. One SpMM pass computes BOTH encodings' layers.
//   - Edges scattered into fixed 64-slot per-row buckets (no hist/scan):
//     pos = r*64 + atomicAdd(cursor[r],1); cursor[r] = row degree afterward.
//   - cursor re-zeroed by extra blocks fused into the pred kernel.
//   - SpMM: persistent warps; EACH HALF-WARP owns one row (warp = rows
//     2w,2w+1). Loop bounds are warp-uniform (max of the pair's degrees);
//     pad edges are zeroed (col 0 -> L1-hot, val 0 -> exact), so no
//     divergence, no final reduction, all 32 lanes store.
//   - Layer 3 only at sampled rows (fp32 accum), fused acc=(ego+X1+X2+X3)/4.
// Output layout: [u_pred | u_target | i_pred | i_target], each [B,64] f32.
// ---------------------------------------------------------------------------

#define D        64
#define HROW     64          // half2 per node row (128 halfs = 256B)
#define N_NODES  300000
#define EDGE_CAP 64          // bucket capacity per row (max degree ~45)
#define B_MAX    4096
#define SCAT_BLOCKS 4096
#define SPMM_BLOCKS 1184     // 148 SMs * 8 resident CTAs

// Scratch (device globals — no allocation allowed in kernel_launch)
__device__ int     g_cursor[N_NODES];        // zero at load; re-zeroed each call
__device__ int2    g_edges[(size_t)N_NODES * EDGE_CAP];  // {col, half2(v,v)}
__device__ __half2 g_H0[(size_t)N_NODES * HROW];
__device__ __half2 g_H1[(size_t)N_NODES * HROW];
__device__ __half2 g_H2[(size_t)N_NODES * HROW];
__device__ float   g_S[(size_t)2 * B_MAX * D];

static __device__ __forceinline__ unsigned h2_as_u(__half2 h) {
    return *reinterpret_cast<unsigned*>(&h);
}
static __device__ __forceinline__ __half2 u_as_h2(unsigned u) {
    return *reinterpret_cast<__half2*>(&u);
}

// ---------------------------------------------------------------------------
// Fused: bucket scatter (blocks [0,SCAT_BLOCKS)) + ego->fp16 convert (rest).
// ---------------------------------------------------------------------------
__global__ void __launch_bounds__(256) scatter_convert_kernel(
    const int* __restrict__ row, const int* __restrict__ col,
    const float* __restrict__ val, int nnz,
    int* __restrict__ cursor, int2* __restrict__ edges,
    const float2* __restrict__ ue_on, const float2* __restrict__ ie_on,
    const float2* __restrict__ ue_tg, const float2* __restrict__ ie_tg,
    __half2* __restrict__ h0, int n, int usplit)
{
    if (blockIdx.x < SCAT_BLOCKS) {
        int nq = nnz >> 2;
        const int4*   row4 = (const int4*)row;
        const int4*   col4 = (const int4*)col;
        const float4* val4 = (const float4*)val;
        for (int i = blockIdx.x * 256 + threadIdx.x; i < nq;
             i += SCAT_BLOCKS * 256) {
            int4   r = __ldcs(&row4[i]);
            int4   c = __ldcs(&col4[i]);
            float4 v = __ldcs(&val4[i]);
            int p0 = r.x * EDGE_CAP + atomicAdd(&cursor[r.x], 1);
            int p1 = r.y * EDGE_CAP + atomicAdd(&cursor[r.y], 1);
            int p2 = r.z * EDGE_CAP + atomicAdd(&cursor[r.z], 1);
            int p3 = r.w * EDGE_CAP + atomicAdd(&cursor[r.w], 1);
            __stcs(&edges[p0], make_int2(c.x, (int)h2_as_u(__float2half2_rn(v.x))));
            __stcs(&edges[p1], make_int2(c.y, (int)h2_as_u(__float2half2_rn(v.y))));
            __stcs(&edges[p2], make_int2(c.z, (int)h2_as_u(__float2half2_rn(v.z))));
            __stcs(&edges[p3], make_int2(c.w, (int)h2_as_u(__float2half2_rn(v.w))));
        }
        int t = (nq << 2) + blockIdx.x * 256 + threadIdx.x;
        if (t < nnz) {
            int r = __ldcs(&row[t]);
            int pos = r * EDGE_CAP + atomicAdd(&cursor[r], 1);
            __stcs(&edges[pos],
                   make_int2(__ldcs(&col[t]),
                             (int)h2_as_u(__float2half2_rn(__ldcs(&val[t])))));
        }
    } else {
        int idx = (blockIdx.x - SCAT_BLOCKS) * 256 + threadIdx.x;
        if (idx >= n * 32) return;
        int r = idx >> 5;
        int k = idx & 31;
        float2 on, tg;
        if (r < usplit) {
            on = ue_on[(size_t)r * 32 + k];
            tg = ue_tg[(size_t)r * 32 + k];
        } else {
            on = ie_on[(size_t)(r - usplit) * 32 + k];
            tg = ie_tg[(size_t)(r - usplit) * 32 + k];
        }
        h0[(size_t)r * HROW + k]      = __floats2half2_rn(on.x, on.y);
        h0[(size_t)r * HROW + 32 + k] = __floats2half2_rn(tg.x, tg.y);
    }
}

// ---------------------------------------------------------------------------
// Fused SpMM: persistent warps; each HALF-WARP owns one row (warp covers rows
// 2*ww and 2*ww+1). Loop trip counts are warp-uniform (degmax of the pair),
// so the warp never diverges; the shorter row's lanes carry zeroed pad edges
// (col 0 -> node-0 gather, L1-hot; val (0,0) -> HFMA2 adds exactly 0).
// Per chunk each lane loads TWO edges of its row (one int4); 4 edges in
// flight per half-warp (4 independent LDG.128/lane). Pure HFMA2 accum.
// All 32 lanes store (each half-warp stores its own row as 16 uint4).
// ---------------------------------------------------------------------------
__global__ void __launch_bounds__(256) spmm_fused_kernel(
    const int* __restrict__ cursor, const int2* __restrict__ edges,
    const __half2* __restrict__ xin, __half2* __restrict__ xout, int nrows)
{
    int lane = threadIdx.x & 31;
    int half = lane >> 4;
    int hl   = lane & 15;
    int W = (gridDim.x * 256) >> 5;          // total warps
    const char* xbase = (const char*)xin;

    for (int ww = (blockIdx.x * 256 + threadIdx.x) >> 5; 2 * ww < nrows;
         ww += W) {
        int w = 2 * ww + half;               // this half-warp's row
        bool rowvalid = (w < nrows);
        int deg = rowvalid ? __ldg(&cursor[w]) : 0;
        int start = w * EDGE_CAP;
        int degmax = max(deg, __shfl_xor_sync(0xffffffffu, deg, 16));

        __half2 acc0 = u_as_h2(0u), acc1 = u_as_h2(0u);
        __half2 acc2 = u_as_h2(0u), acc3 = u_as_h2(0u);

        for (int base = 0; base < degmax; base += 32) {
            // each lane loads edges (base+2*hl, base+2*hl+1) of ITS row
            int e0 = base + 2 * hl;
            int4 ee = make_int4(0, 0, 0, 0);
            if (e0 < deg) {
                ee = __ldcs((const int4*)(edges + start + e0));
                if (e0 + 1 >= deg) { ee.z = 0; ee.w = 0; }
            }
            int cmax = min(32, degmax - base);
            for (int j = 0; j < cmax; j += 4) {
                int srcL = (half << 4) + (j >> 1);
                int      cA = __shfl_sync(0xffffffffu, ee.x, srcL);
                unsigned vA = (unsigned)__shfl_sync(0xffffffffu, ee.y, srcL);
                int      cB = __shfl_sync(0xffffffffu, ee.z, srcL);
                unsigned vB = (unsigned)__shfl_sync(0xffffffffu, ee.w, srcL);
                int      cC = __shfl_sync(0xffffffffu, ee.x, srcL + 1);
                unsigned vC = (unsigned)__shfl_sync(0xffffffffu, ee.y, srcL + 1);
                int      cD = __shfl_sync(0xffffffffu, ee.z, srcL + 1);
                unsigned vD = (unsigned)__shfl_sync(0xffffffffu, ee.w, srcL + 1);

                uint4 rA = __ldg((const uint4*)(xbase + (size_t)cA * 256 + hl * 16));
                uint4 rB = __ldg((const uint4*)(xbase + (size_t)cB * 256 + hl * 16));
                uint4 rC = __ldg((const uint4*)(xbase + (size_t)cC * 256 + hl * 16));
                uint4 rD = __ldg((const uint4*)(xbase + (size_t)cD * 256 + hl * 16));

                __half2 vhA = u_as_h2(vA), vhB = u_as_h2(vB);
                __half2 vhC = u_as_h2(vC), vhD = u_as_h2(vD);

                acc0 = __hfma2(u_as_h2(rA.x), vhA, acc0);
                acc1 = __hfma2(u_as_h2(rA.y), vhA, acc1);
                acc2 = __hfma2(u_as_h2(rA.z), vhA, acc2);
                acc3 = __hfma2(u_as_h2(rA.w), vhA, acc3);

                acc0 = __hfma2(u_as_h2(rB.x), vhB, acc0);
                acc1 = __hfma2(u_as_h2(rB.y), vhB, acc1);
                acc2 = __hfma2(u_as_h2(rB.z), vhB, acc2);
                acc3 = __hfma2(u_as_h2(rB.w), vhB, acc3);

                acc0 = __hfma2(u_as_h2(rC.x), vhC, acc0);
                acc1 = __hfma2(u_as_h2(rC.y), vhC, acc1);
                acc2 = __hfma2(u_as_h2(rC.z), vhC, acc2);
                acc3 = __hfma2(u_as_h2(rC.w), vhC, acc3);

                acc0 = __hfma2(u_as_h2(rD.x), vhD, acc0);
                acc1 = __hfma2(u_as_h2(rD.y), vhD, acc1);
                acc2 = __hfma2(u_as_h2(rD.z), vhD, acc2);
                acc3 = __hfma2(u_as_h2(rD.w), vhD, acc3);
            }
        }

        if (rowvalid) {
            uint4 o;
            o.x = h2_as_u(acc0);
            o.y = h2_as_u(acc1);
            o.z = h2_as_u(acc2);
            o.w = h2_as_u(acc3);
            __stcs((uint4*)((char*)xout + (size_t)w * 256 + hl * 16), o);
        }
    }
}

// ---------------------------------------------------------------------------
// Layer-3 at sampled rows (both encodings), fp32 accumulation, fused with
// acc = 0.25*(ego_fp32 + X1 + X2 + X3). Online acc -> S, target acc -> out.
// ---------------------------------------------------------------------------
__global__ void __launch_bounds__(256) sampled_fused_kernel(
    const int* __restrict__ cursor, const int2* __restrict__ edges,
    const __half2* __restrict__ h1, const __half2* __restrict__ h2,
    const float2* __restrict__ ue_on, const float2* __restrict__ ie_on,
    const float2* __restrict__ ue_tg, const float2* __restrict__ ie_tg,
    const int* __restrict__ user_idx, const int* __restrict__ item_idx,
    float2* __restrict__ s_on,
    float2* __restrict__ out_utg, float2* __restrict__ out_itg,
    int b, int usplit)
{
    int s = (blockIdx.x * 256 + threadIdx.x) >> 5;
    if (s >= 2 * b) return;
    int lane = threadIdx.x & 31;
    int r = (s < b) ? __ldg(&user_idx[s]) : usplit + __ldg(&item_idx[s - b]);

    int start = r * EDGE_CAP;
    int end   = start + __ldg(&cursor[r]);
    float2 aon = make_float2(0.f, 0.f);
    float2 atg = make_float2(0.f, 0.f);
    for (int base = start; base < end; base += 32) {
        int2 ev = make_int2(0, 0);
        if (base + lane < end) ev = edges[base + lane];
        int cnt = min(32, end - base);
        for (int j = 0; j < cnt; j += 2) {
            int      cA = __shfl_sync(0xffffffffu, ev.x, j);
            unsigned uA = (unsigned)__shfl_sync(0xffffffffu, ev.y, j);
            int      cB = __shfl_sync(0xffffffffu, ev.x, j + 1);
            unsigned uB = (unsigned)__shfl_sync(0xffffffffu, ev.y, j + 1);
            float vA = __half2float(__low2half(u_as_h2(uA)));
            float vB = __half2float(__low2half(u_as_h2(uB)));
            const __half2* sA = h2 + (size_t)cA * HROW;
            const __half2* sB = h2 + (size_t)cB * HROW;
            float2 a  = __half22float2(__ldg(sA + lane));
            float2 t  = __half22float2(__ldg(sA + 32 + lane));
            float2 a2 = __half22float2(__ldg(sB + lane));
            float2 t2 = __half22float2(__ldg(sB + 32 + lane));
            aon.x = fmaf(vA, a.x, aon.x);
            aon.y = fmaf(vA, a.y, aon.y);
            atg.x = fmaf(vA, t.x, atg.x);
            atg.y = fmaf(vA, t.y, atg.y);
            aon.x = fmaf(vB, a2.x, aon.x);
            aon.y = fmaf(vB, a2.y, aon.y);
            atg.x = fmaf(vB, t2.x, atg.x);
            atg.y = fmaf(vB, t2.y, atg.y);
        }
    }

    float2 e_on = (r < usplit) ? __ldg(&ue_on[(size_t)r * 32 + lane])
                               : __ldg(&ie_on[(size_t)(r - usplit) * 32 + lane]);
    float2 e_tg = (r < usplit) ? __ldg(&ue_tg[(size_t)r * 32 + lane])
                               : __ldg(&ie_tg[(size_t)(r - usplit) * 32 + lane]);
    float2 x1on = __half22float2(__ldg(h1 + (size_t)r * HROW + lane));
    float2 x1tg = __half22float2(__ldg(h1 + (size_t)r * HROW + 32 + lane));
    float2 x2on = __half22float2(__ldg(h2 + (size_t)r * HROW + lane));
    float2 x2tg = __half22float2(__ldg(h2 + (size_t)r * HROW + 32 + lane));

    float2 ron, rtg;
    ron.x = 0.25f * (e_on.x + x1on.x + x2on.x + aon.x);
    ron.y = 0.25f * (e_on.y + x1on.y + x2on.y + aon.y);
    rtg.x = 0.25f * (e_tg.x + x1tg.x + x2tg.x + atg.x);
    rtg.y = 0.25f * (e_tg.y + x1tg.y + x2tg.y + atg.y);

    s_on[(size_t)s * 32 + lane] = ron;
    float2* dtg = (s < b) ? (out_utg + (size_t)s * 32 + lane)
                          : (out_itg + (size_t)(s - b) * 32 + lane);
    *dtg = rtg;
}

// ---------------------------------------------------------------------------
// Linear head (blocks [0,pb)) + cursor re-zero (blocks >= pb) for next call.
// ---------------------------------------------------------------------------
__global__ void __launch_bounds__(256) pred_zero_kernel(
    const float* __restrict__ S, const float* __restrict__ W,
    const float* __restrict__ bias,
    float* __restrict__ out_u, float* __restrict__ out_i, int b, int pb,
    int* __restrict__ cursor, int n)
{
    int tx = threadIdx.x, ty = threadIdx.y;
    int tid = ty * 64 + tx;

    if ((int)blockIdx.x >= pb) {               // cursor zeroing branch
        int i = (blockIdx.x - pb) * 256 + tid;
        if (i < n) cursor[i] = 0;
        return;
    }

    __shared__ float Wt[64][65];
    __shared__ float srow[4][64];
    __shared__ float sb[64];
    for (int idx = tid; idx < 4096; idx += 256)
        Wt[idx & 63][idx >> 6] = W[idx];
    if (tid < 64) sb[tid] = bias[tid];
    int s = blockIdx.x * 4 + ty;
    srow[ty][tx] = S[(size_t)s * 64 + tx];
    __syncthreads();

    float acc = sb[tx];
    #pragma unroll
    for (int k = 0; k < 64; k++)
        acc = fmaf(srow[ty][k], Wt[k][tx], acc);

    float* d = (s < b) ? (out_u + (size_t)s * 64 + tx)
                       : (out_i + (size_t)(s - b) * 64 + tx);
    *d = acc;
}

// ---------------------------------------------------------------------------
// Launch
// ---------------------------------------------------------------------------
extern "C" void kernel_launch(void* const* d_in, const int* in_sizes, int n_in,
                              void* d_out, int out_size) {
    const float* ue_on   = (const float*)d_in[0];
    const float* ie_on   = (const float*)d_in[1];
    const float* ue_tg   = (const float*)d_in[2];
    const float* ie_tg   = (const float*)d_in[3];
    const float* adj_val = (const float*)d_in[4];
    const float* pred_w  = (const float*)d_in[5];
    const float* pred_b  = (const float*)d_in[6];
    const int*   adj_row = (const int*)d_in[7];
    const int*   adj_col = (const int*)d_in[8];
    const int*   user_idx = (const int*)d_in[9];
    const int*   item_idx = (const int*)d_in[10];

    int uN  = in_sizes[0] / D;
    int iN  = in_sizes[1] / D;
    int n   = uN + iN;
    int nnz = in_sizes[4];
    int b   = in_sizes[9];

    int* cursor;
    int2* edges;
    __half2 *h0, *h1, *h2;
    float* S;
    cudaGetSymbolAddress((void**)&cursor, g_cursor);
    cudaGetSymbolAddress((void**)&edges,  g_edges);
    cudaGetSymbolAddress((void**)&h0,     g_H0);
    cudaGetSymbolAddress((void**)&h1,     g_H1);
    cudaGetSymbolAddress((void**)&h2,     g_H2);
    cudaGetSymbolAddress((void**)&S,      g_S);

    // --- bucket scatter + ego conversion (cursor pre-zeroed by prev call) ---
    int conv_blocks = (n * 32 + 255) / 256;
    scatter_convert_kernel<<<SCAT_BLOCKS + conv_blocks, 256>>>(
        adj_row, adj_col, adj_val, nnz, cursor, edges,
        (const float2*)ue_on, (const float2*)ie_on,
        (const float2*)ue_tg, (const float2*)ie_tg, h0, n, uN);

    int samp_blocks = (2 * b + 7) / 8;
    float* out = (float*)d_out;
    size_t BD = (size_t)b * D;

    spmm_fused_kernel<<<SPMM_BLOCKS, 256>>>(cursor, edges, h0, h1, n);
    spmm_fused_kernel<<<SPMM_BLOCKS, 256>>>(cursor, edges, h1, h2, n);
    sampled_fused_kernel<<<samp_blocks, 256>>>(cursor, edges, h1, h2,
        (const float2*)ue_on, (const float2*)ie_on,
        (const float2*)ue_tg, (const float2*)ie_tg,
        user_idx, item_idx,
        (float2*)S,
        (float2*)(out + BD),
        (float2*)(out + 3 * BD),
        b, uN);
    int pb = (2 * b) / 4;
    int zero_blocks = (n + 255) / 256;
    pred_zero_kernel<<<pb + zero_blocks, dim3(64, 4)>>>(S, pred_w, pred_b,
        out, out + 2 * BD, b, pb, cursor, n);
}

// round 15
// speedup vs baseline: 1.0675x; 1.0675x over previous
#include <cuda_runtime.h>
#include <cuda_fp16.h>

// ---------------------------------------------------------------------------
// BUIR / LightGCN forward, all-fp16 HFMA2 SpMM, bucketed CSR (round-12 core).
//   - Online+target embeddings interleaved per node: H[r] = [64 on | 64 tg]
//     fp16 = 256B row. One SpMM pass computes BOTH encodings' layers.
//   - Edges scattered into fixed 64-slot per-row buckets (no hist/scan):
//     pos = r*64 + atomicAdd(cursor[r],1); cursor[r] = row degree afterward.
//     Edge col is stored PRE-SCALED to a byte offset (col*256) so gathers
//     need no IMAD. Edge value pre-duplicated as packed half2 (v,v).
//   - cursor re-zeroed by extra blocks fused into the pred kernel.
//   - SpMM: persistent warps (148*8 CTAs), warp per row, 8 edges in flight
//     (4 independent LDG.128/lane), pure HFMA2 accumulation.
//   - Layer 3 only at sampled rows (fp32 accum), fused acc=(ego+X1+X2+X3)/4.
//     (R14 bug fixed: half2 lane offset is lane*4 bytes, NOT lane*8.)
// Output layout: [u_pred | u_target | i_pred | i_target], each [B,64] f32.
// ---------------------------------------------------------------------------

#define D        64
#define HROW     64          // half2 per node row (128 halfs = 256B)
#define N_NODES  300000
#define EDGE_CAP 64          // bucket capacity per row (max degree ~45)
#define B_MAX    4096
#define SCAT_BLOCKS 4096
#define SPMM_BLOCKS 1184     // 148 SMs * 8 resident CTAs

// Scratch (device globals — no allocation allowed in kernel_launch)
__device__ int     g_cursor[N_NODES];        // zero at load; re-zeroed each call
__device__ int2    g_edges[(size_t)N_NODES * EDGE_CAP];  // {col*256, half2(v,v)}
__device__ __half2 g_H0[(size_t)N_NODES * HROW];
__device__ __half2 g_H1[(size_t)N_NODES * HROW];
__device__ __half2 g_H2[(size_t)N_NODES * HROW];
__device__ float   g_S[(size_t)2 * B_MAX * D];

static __device__ __forceinline__ unsigned h2_as_u(__half2 h) {
    return *reinterpret_cast<unsigned*>(&h);
}
static __device__ __forceinline__ __half2 u_as_h2(unsigned u) {
    return *reinterpret_cast<__half2*>(&u);
}

// ---------------------------------------------------------------------------
// Fused: bucket scatter (blocks [0,SCAT_BLOCKS)) + ego->fp16 convert (rest).
// ---------------------------------------------------------------------------
__global__ void __launch_bounds__(256) scatter_convert_kernel(
    const int* __restrict__ row, const int* __restrict__ col,
    const float* __restrict__ val, int nnz,
    int* __restrict__ cursor, int2* __restrict__ edges,
    const float2* __restrict__ ue_on, const float2* __restrict__ ie_on,
    const float2* __restrict__ ue_tg, const float2* __restrict__ ie_tg,
    __half2* __restrict__ h0, int n, int usplit)
{
    if (blockIdx.x < SCAT_BLOCKS) {
        int nq = nnz >> 2;
        const int4*   row4 = (const int4*)row;
        const int4*   col4 = (const int4*)col;
        const float4* val4 = (const float4*)val;
        for (int i = blockIdx.x * 256 + threadIdx.x; i < nq;
             i += SCAT_BLOCKS * 256) {
            int4   r = __ldcs(&row4[i]);
            int4   c = __ldcs(&col4[i]);
            float4 v = __ldcs(&val4[i]);
            int p0 = r.x * EDGE_CAP + atomicAdd(&cursor[r.x], 1);
            int p1 = r.y * EDGE_CAP + atomicAdd(&cursor[r.y], 1);
            int p2 = r.z * EDGE_CAP + atomicAdd(&cursor[r.z], 1);
            int p3 = r.w * EDGE_CAP + atomicAdd(&cursor[r.w], 1);
            __stcs(&edges[p0], make_int2(c.x << 8, (int)h2_as_u(__float2half2_rn(v.x))));
            __stcs(&edges[p1], make_int2(c.y << 8, (int)h2_as_u(__float2half2_rn(v.y))));
            __stcs(&edges[p2], make_int2(c.z << 8, (int)h2_as_u(__float2half2_rn(v.z))));
            __stcs(&edges[p3], make_int2(c.w << 8, (int)h2_as_u(__float2half2_rn(v.w))));
        }
        int t = (nq << 2) + blockIdx.x * 256 + threadIdx.x;
        if (t < nnz) {
            int r = __ldcs(&row[t]);
            int pos = r * EDGE_CAP + atomicAdd(&cursor[r], 1);
            __stcs(&edges[pos],
                   make_int2(__ldcs(&col[t]) << 8,
                             (int)h2_as_u(__float2half2_rn(__ldcs(&val[t])))));
        }
    } else {
        int idx = (blockIdx.x - SCAT_BLOCKS) * 256 + threadIdx.x;
        if (idx >= n * 32) return;
        int r = idx >> 5;
        int k = idx & 31;
        float2 on, tg;
        if (r < usplit) {
            on = ue_on[(size_t)r * 32 + k];
            tg = ue_tg[(size_t)r * 32 + k];
        } else {
            on = ie_on[(size_t)(r - usplit) * 32 + k];
            tg = ie_tg[(size_t)(r - usplit) * 32 + k];
        }
        h0[(size_t)r * HROW + k]      = __floats2half2_rn(on.x, on.y);
        h0[(size_t)r * HROW + 32 + k] = __floats2half2_rn(tg.x, tg.y);
    }
}

// ---------------------------------------------------------------------------
// Fused SpMM (round-12 core): persistent warps grid-striding; warp per row.
// Row w's edges live at [w*EDGE_CAP, w*EDGE_CAP + cursor[w]); edge.x is the
// source row's BYTE offset. 8 edges in flight (4 independent LDG.128/lane),
// pure HFMA2. Pad lanes carry ev=(0,0): v-half2=(0,0) keeps HFMA2 exact; pad
// gathers hit node 0 (L1-hot). shfl_xor(16)+HADD2 combine; lanes 0-15 store.
// ---------------------------------------------------------------------------
__global__ void __launch_bounds__(256) spmm_fused_kernel(
    const int* __restrict__ cursor, const int2* __restrict__ edges,
    const __half2* __restrict__ xin, __half2* __restrict__ xout, int nrows)
{
    int lane = threadIdx.x & 31;
    int half = lane >> 4;
    int hl   = lane & 15;
    int wstep = (gridDim.x * 256) >> 5;
    const char* xbase = (const char*)xin + hl * 16;   // fold lane offset in

    for (int w = (blockIdx.x * 256 + threadIdx.x) >> 5; w < nrows; w += wstep) {
        int start = w * EDGE_CAP;
        int end   = start + __ldg(&cursor[w]);

        __half2 acc0 = u_as_h2(0u), acc1 = u_as_h2(0u);
        __half2 acc2 = u_as_h2(0u), acc3 = u_as_h2(0u);

        for (int base = start; base < end; base += 32) {
            int2 ev = make_int2(0, 0);             // pad: off 0 / val (0,0)
            if (base + lane < end) ev = __ldcs(&edges[base + lane]);
            int cnt = min(32, end - base);
            for (int j = 0; j < cnt; j += 8) {
                int      cA = __shfl_sync(0xffffffffu, ev.x, j + half);
                unsigned vA = (unsigned)__shfl_sync(0xffffffffu, ev.y, j + half);
                int      cB = __shfl_sync(0xffffffffu, ev.x, j + 2 + half);
                unsigned vB = (unsigned)__shfl_sync(0xffffffffu, ev.y, j + 2 + half);
                int      cC = __shfl_sync(0xffffffffu, ev.x, j + 4 + half);
                unsigned vC = (unsigned)__shfl_sync(0xffffffffu, ev.y, j + 4 + half);
                int      cD = __shfl_sync(0xffffffffu, ev.x, j + 6 + half);
                unsigned vD = (unsigned)__shfl_sync(0xffffffffu, ev.y, j + 6 + half);

                uint4 rA = __ldg((const uint4*)(xbase + cA));
                uint4 rB = __ldg((const uint4*)(xbase + cB));
                uint4 rC = __ldg((const uint4*)(xbase + cC));
                uint4 rD = __ldg((const uint4*)(xbase + cD));

                __half2 vhA = u_as_h2(vA), vhB = u_as_h2(vB);
                __half2 vhC = u_as_h2(vC), vhD = u_as_h2(vD);

                acc0 = __hfma2(u_as_h2(rA.x), vhA, acc0);
                acc1 = __hfma2(u_as_h2(rA.y), vhA, acc1);
                acc2 = __hfma2(u_as_h2(rA.z), vhA, acc2);
                acc3 = __hfma2(u_as_h2(rA.w), vhA, acc3);

                acc0 = __hfma2(u_as_h2(rB.x), vhB, acc0);
                acc1 = __hfma2(u_as_h2(rB.y), vhB, acc1);
                acc2 = __hfma2(u_as_h2(rB.z), vhB, acc2);
                acc3 = __hfma2(u_as_h2(rB.w), vhB, acc3);

                acc0 = __hfma2(u_as_h2(rC.x), vhC, acc0);
                acc1 = __hfma2(u_as_h2(rC.y), vhC, acc1);
                acc2 = __hfma2(u_as_h2(rC.z), vhC, acc2);
                acc3 = __hfma2(u_as_h2(rC.w), vhC, acc3);

                acc0 = __hfma2(u_as_h2(rD.x), vhD, acc0);
                acc1 = __hfma2(u_as_h2(rD.y), vhD, acc1);
                acc2 = __hfma2(u_as_h2(rD.z), vhD, acc2);
                acc3 = __hfma2(u_as_h2(rD.w), vhD, acc3);
            }
        }

        acc0 = __hadd2(acc0, u_as_h2(__shfl_xor_sync(0xffffffffu, h2_as_u(acc0), 16)));
        acc1 = __hadd2(acc1, u_as_h2(__shfl_xor_sync(0xffffffffu, h2_as_u(acc1), 16)));
        acc2 = __hadd2(acc2, u_as_h2(__shfl_xor_sync(0xffffffffu, h2_as_u(acc2), 16)));
        acc3 = __hadd2(acc3, u_as_h2(__shfl_xor_sync(0xffffffffu, h2_as_u(acc3), 16)));

        if (lane < 16) {
            uint4 o;
            o.x = h2_as_u(acc0);
            o.y = h2_as_u(acc1);
            o.z = h2_as_u(acc2);
            o.w = h2_as_u(acc3);
            __stcs((uint4*)((char*)xout + (size_t)w * 256 + hl * 16), o);
        }
    }
}

// ---------------------------------------------------------------------------
// Layer-3 at sampled rows (both encodings), fp32 accumulation, fused with
// acc = 0.25*(ego_fp32 + X1 + X2 + X3). Online acc -> S, target acc -> out.
// edge.x is a byte offset into the node array. half2 lane offset = lane*4 B.
// ---------------------------------------------------------------------------
__global__ void __launch_bounds__(256) sampled_fused_kernel(
    const int* __restrict__ cursor, const int2* __restrict__ edges,
    const __half2* __restrict__ h1, const __half2* __restrict__ h2,
    const float2* __restrict__ ue_on, const float2* __restrict__ ie_on,
    const float2* __restrict__ ue_tg, const float2* __restrict__ ie_tg,
    const int* __restrict__ user_idx, const int* __restrict__ item_idx,
    float2* __restrict__ s_on,
    float2* __restrict__ out_utg, float2* __restrict__ out_itg,
    int b, int usplit)
{
    int s = (blockIdx.x * 256 + threadIdx.x) >> 5;
    if (s >= 2 * b) return;
    int lane = threadIdx.x & 31;
    int r = (s < b) ? __ldg(&user_idx[s]) : usplit + __ldg(&item_idx[s - b]);

    int start = r * EDGE_CAP;
    int end   = start + __ldg(&cursor[r]);
    const char* x2base = (const char*)h2 + lane * 4;   // half2 = 4 bytes!
    float2 aon = make_float2(0.f, 0.f);
    float2 atg = make_float2(0.f, 0.f);
    for (int base = start; base < end; base += 32) {
        int2 ev = make_int2(0, 0);
        if (base + lane < end) ev = edges[base + lane];
        int cnt = min(32, end - base);
        for (int j = 0; j < cnt; j += 2) {
            int      cA = __shfl_sync(0xffffffffu, ev.x, j);
            unsigned uA = (unsigned)__shfl_sync(0xffffffffu, ev.y, j);
            int      cB = __shfl_sync(0xffffffffu, ev.x, j + 1);
            unsigned uB = (unsigned)__shfl_sync(0xffffffffu, ev.y, j + 1);
            float vA = __half2float(__low2half(u_as_h2(uA)));
            float vB = __half2float(__low2half(u_as_h2(uB)));
            float2 a  = __half22float2(__ldg((const __half2*)(x2base + cA)));
            float2 t  = __half22float2(__ldg((const __half2*)(x2base + cA + 128)));
            float2 a2 = __half22float2(__ldg((const __half2*)(x2base + cB)));
            float2 t2 = __half22float2(__ldg((const __half2*)(x2base + cB + 128)));
            aon.x = fmaf(vA, a.x, aon.x);
            aon.y = fmaf(vA, a.y, aon.y);
            atg.x = fmaf(vA, t.x, atg.x);
            atg.y = fmaf(vA, t.y, atg.y);
            aon.x = fmaf(vB, a2.x, aon.x);
            aon.y = fmaf(vB, a2.y, aon.y);
            atg.x = fmaf(vB, t2.x, atg.x);
            atg.y = fmaf(vB, t2.y, atg.y);
        }
    }

    float2 e_on = (r < usplit) ? __ldg(&ue_on[(size_t)r * 32 + lane])
                               : __ldg(&ie_on[(size_t)(r - usplit) * 32 + lane]);
    float2 e_tg = (r < usplit) ? __ldg(&ue_tg[(size_t)r * 32 + lane])
                               : __ldg(&ie_tg[(size_t)(r - usplit) * 32 + lane]);
    float2 x1on = __half22float2(__ldg(h1 + (size_t)r * HROW + lane));
    float2 x1tg = __half22float2(__ldg(h1 + (size_t)r * HROW + 32 + lane));
    float2 x2on = __half22float2(__ldg(h2 + (size_t)r * HROW + lane));
    float2 x2tg = __half22float2(__ldg(h2 + (size_t)r * HROW + 32 + lane));

    float2 ron, rtg;
    ron.x = 0.25f * (e_on.x + x1on.x + x2on.x + aon.x);
    ron.y = 0.25f * (e_on.y + x1on.y + x2on.y + aon.y);
    rtg.x = 0.25f * (e_tg.x + x1tg.x + x2tg.x + atg.x);
    rtg.y = 0.25f * (e_tg.y + x1tg.y + x2tg.y + atg.y);

    s_on[(size_t)s * 32 + lane] = ron;
    float2* dtg = (s < b) ? (out_utg + (size_t)s * 32 + lane)
                          : (out_itg + (size_t)(s - b) * 32 + lane);
    *dtg = rtg;
}

// ---------------------------------------------------------------------------
// Linear head (blocks [0,pb)) + cursor re-zero (blocks >= pb) for next call.
// ---------------------------------------------------------------------------
__global__ void __launch_bounds__(256) pred_zero_kernel(
    const float* __restrict__ S, const float* __restrict__ W,
    const float* __restrict__ bias,
    float* __restrict__ out_u, float* __restrict__ out_i, int b, int pb,
    int* __restrict__ cursor, int n)
{
    int tx = threadIdx.x, ty = threadIdx.y;
    int tid = ty * 64 + tx;

    if ((int)blockIdx.x >= pb) {               // cursor zeroing branch
        int i = (blockIdx.x - pb) * 256 + tid;
        if (i < n) cursor[i] = 0;
        return;
    }

    __shared__ float Wt[64][65];
    __shared__ float srow[4][64];
    __shared__ float sb[64];
    for (int idx = tid; idx < 4096; idx += 256)
        Wt[idx & 63][idx >> 6] = W[idx];
    if (tid < 64) sb[tid] = bias[tid];
    int s = blockIdx.x * 4 + ty;
    srow[ty][tx] = S[(size_t)s * 64 + tx];
    __syncthreads();

    float acc = sb[tx];
    #pragma unroll
    for (int k = 0; k < 64; k++)
        acc = fmaf(srow[ty][k], Wt[k][tx], acc);

    float* d = (s < b) ? (out_u + (size_t)s * 64 + tx)
                       : (out_i + (size_t)(s - b) * 64 + tx);
    *d = acc;
}

// ---------------------------------------------------------------------------
// Launch
// ---------------------------------------------------------------------------
extern "C" void kernel_launch(void* const* d_in, const int* in_sizes, int n_in,
                              void* d_out, int out_size) {
    const float* ue_on   = (const float*)d_in[0];
    const float* ie_on   = (const float*)d_in[1];
    const float* ue_tg   = (const float*)d_in[2];
    const float* ie_tg   = (const float*)d_in[3];
    const float* adj_val = (const float*)d_in[4];
    const float* pred_w  = (const float*)d_in[5];
    const float* pred_b  = (const float*)d_in[6];
    const int*   adj_row = (const int*)d_in[7];
    const int*   adj_col = (const int*)d_in[8];
    const int*   user_idx = (const int*)d_in[9];
    const int*   item_idx = (const int*)d_in[10];

    int uN  = in_sizes[0] / D;
    int iN  = in_sizes[1] / D;
    int n   = uN + iN;
    int nnz = in_sizes[4];
    int b   = in_sizes[9];

    int* cursor;
    int2* edges;
    __half2 *h0, *h1, *h2;
    float* S;
    cudaGetSymbolAddress((void**)&cursor, g_cursor);
    cudaGetSymbolAddress((void**)&edges,  g_edges);
    cudaGetSymbolAddress((void**)&h0,     g_H0);
    cudaGetSymbolAddress((void**)&h1,     g_H1);
    cudaGetSymbolAddress((void**)&h2,     g_H2);
    cudaGetSymbolAddress((void**)&S,      g_S);

    // --- bucket scatter + ego conversion (cursor pre-zeroed by prev call) ---
    int conv_blocks = (n * 32 + 255) / 256;
    scatter_convert_kernel<<<SCAT_BLOCKS + conv_blocks, 256>>>(
        adj_row, adj_col, adj_val, nnz, cursor, edges,
        (const float2*)ue_on, (const float2*)ie_on,
        (const float2*)ue_tg, (const float2*)ie_tg, h0, n, uN);

    int samp_blocks = (2 * b + 7) / 8;
    float* out = (float*)d_out;
    size_t BD = (size_t)b * D;

    spmm_fused_kernel<<<SPMM_BLOCKS, 256>>>(cursor, edges, h0, h1, n);
    spmm_fused_kernel<<<SPMM_BLOCKS, 256>>>(cursor, edges, h1, h2, n);
    sampled_fused_kernel<<<samp_blocks, 256>>>(cursor, edges, h1, h2,
        (const float2*)ue_on, (const float2*)ie_on,
        (const float2*)ue_tg, (const float2*)ie_tg,
        user_idx, item_idx,
        (float2*)S,
        (float2*)(out + BD),
        (float2*)(out + 3 * BD),
        b, uN);
    int pb = (2 * b) / 4;
    int zero_blocks = (n + 255) / 256;
    pred_zero_kernel<<<pb + zero_blocks, dim3(64, 4)>>>(S, pred_w, pred_b,
        out, out + 2 * BD, b, pb, cursor, n);
}

// round 16
// speedup vs baseline: 1.1287x; 1.0574x over previous
#include <cuda_runtime.h>
#include <cuda_fp16.h>

// ---------------------------------------------------------------------------
// BUIR / LightGCN forward, all-fp16 HFMA2 SpMM, bucketed CSR (round-12 core).
//   - Online+target embeddings interleaved per node: H[r] = [64 on | 64 tg]
//     fp16 = 256B row. One SpMM pass computes BOTH encodings' layers.
//   - Edges scattered into fixed 64-slot per-row buckets (no hist/scan):
//     pos = r*64 + atomicAdd(cursor[r],1); cursor[r] = row degree afterward.
//     Edge value pre-duplicated as packed half2 (v,v). Edge col stored as a
//     plain index (IMAD.WIDE scaled addressing beats pre-scaled offsets).
//   - cursor re-zeroed by extra blocks fused into the pred kernel.
//   - Scatter: 8 edges per thread (2x int4/float4) for doubled ATOMG MLP.
//   - SpMM: persistent warps (148*8 CTAs), warp per row, 8 edges in flight
//     (4 independent LDG.128/lane), pure HFMA2 accumulation.
//   - Layer 3 only at sampled rows (fp32 accum), fused acc=(ego+X1+X2+X3)/4.
// Output layout: [u_pred | u_target | i_pred | i_target], each [B,64] f32.
// ---------------------------------------------------------------------------

#define D        64
#define HROW     64          // half2 per node row (128 halfs = 256B)
#define N_NODES  300000
#define EDGE_CAP 64          // bucket capacity per row (max degree ~45)
#define B_MAX    4096
#define SCAT_BLOCKS 4096
#define SPMM_BLOCKS 1184     // 148 SMs * 8 resident CTAs

// Scratch (device globals — no allocation allowed in kernel_launch)
__device__ int     g_cursor[N_NODES];        // zero at load; re-zeroed each call
__device__ int2    g_edges[(size_t)N_NODES * EDGE_CAP];  // {col, half2(v,v)}
__device__ __half2 g_H0[(size_t)N_NODES * HROW];
__device__ __half2 g_H1[(size_t)N_NODES * HROW];
__device__ __half2 g_H2[(size_t)N_NODES * HROW];
__device__ float   g_S[(size_t)2 * B_MAX * D];

static __device__ __forceinline__ unsigned h2_as_u(__half2 h) {
    return *reinterpret_cast<unsigned*>(&h);
}
static __device__ __forceinline__ __half2 u_as_h2(unsigned u) {
    return *reinterpret_cast<__half2*>(&u);
}

// ---------------------------------------------------------------------------
// Fused: bucket scatter (blocks [0,SCAT_BLOCKS)) + ego->fp16 convert (rest).
// Scatter: 8 edges per thread via two int4/float4 triplets (doubled MLP).
// ---------------------------------------------------------------------------
__global__ void __launch_bounds__(256) scatter_convert_kernel(
    const int* __restrict__ row, const int* __restrict__ col,
    const float* __restrict__ val, int nnz,
    int* __restrict__ cursor, int2* __restrict__ edges,
    const float2* __restrict__ ue_on, const float2* __restrict__ ie_on,
    const float2* __restrict__ ue_tg, const float2* __restrict__ ie_tg,
    __half2* __restrict__ h0, int n, int usplit)
{
    if (blockIdx.x < SCAT_BLOCKS) {
        int n8 = nnz >> 3;                         // 8-edge chunks
        const int4*   row4 = (const int4*)row;
        const int4*   col4 = (const int4*)col;
        const float4* val4 = (const float4*)val;
        for (int i = blockIdx.x * 256 + threadIdx.x; i < n8;
             i += SCAT_BLOCKS * 256) {
            int4   r0 = __ldcs(&row4[2 * i]);
            int4   r1 = __ldcs(&row4[2 * i + 1]);
            int4   c0 = __ldcs(&col4[2 * i]);
            int4   c1 = __ldcs(&col4[2 * i + 1]);
            float4 v0 = __ldcs(&val4[2 * i]);
            float4 v1 = __ldcs(&val4[2 * i + 1]);
            int p0 = r0.x * EDGE_CAP + atomicAdd(&cursor[r0.x], 1);
            int p1 = r0.y * EDGE_CAP + atomicAdd(&cursor[r0.y], 1);
            int p2 = r0.z * EDGE_CAP + atomicAdd(&cursor[r0.z], 1);
            int p3 = r0.w * EDGE_CAP + atomicAdd(&cursor[r0.w], 1);
            int p4 = r1.x * EDGE_CAP + atomicAdd(&cursor[r1.x], 1);
            int p5 = r1.y * EDGE_CAP + atomicAdd(&cursor[r1.y], 1);
            int p6 = r1.z * EDGE_CAP + atomicAdd(&cursor[r1.z], 1);
            int p7 = r1.w * EDGE_CAP + atomicAdd(&cursor[r1.w], 1);
            __stcs(&edges[p0], make_int2(c0.x, (int)h2_as_u(__float2half2_rn(v0.x))));
            __stcs(&edges[p1], make_int2(c0.y, (int)h2_as_u(__float2half2_rn(v0.y))));
            __stcs(&edges[p2], make_int2(c0.z, (int)h2_as_u(__float2half2_rn(v0.z))));
            __stcs(&edges[p3], make_int2(c0.w, (int)h2_as_u(__float2half2_rn(v0.w))));
            __stcs(&edges[p4], make_int2(c1.x, (int)h2_as_u(__float2half2_rn(v1.x))));
            __stcs(&edges[p5], make_int2(c1.y, (int)h2_as_u(__float2half2_rn(v1.y))));
            __stcs(&edges[p6], make_int2(c1.z, (int)h2_as_u(__float2half2_rn(v1.z))));
            __stcs(&edges[p7], make_int2(c1.w, (int)h2_as_u(__float2half2_rn(v1.w))));
        }
        int t = (n8 << 3) + blockIdx.x * 256 + threadIdx.x;
        if (t < nnz) {
            int r = __ldcs(&row[t]);
            int pos = r * EDGE_CAP + atomicAdd(&cursor[r], 1);
            __stcs(&edges[pos],
                   make_int2(__ldcs(&col[t]),
                             (int)h2_as_u(__float2half2_rn(__ldcs(&val[t])))));
        }
    } else {
        int idx = (blockIdx.x - SCAT_BLOCKS) * 256 + threadIdx.x;
        if (idx >= n * 32) return;
        int r = idx >> 5;
        int k = idx & 31;
        float2 on, tg;
        if (r < usplit) {
            on = ue_on[(size_t)r * 32 + k];
            tg = ue_tg[(size_t)r * 32 + k];
        } else {
            on = ie_on[(size_t)(r - usplit) * 32 + k];
            tg = ie_tg[(size_t)(r - usplit) * 32 + k];
        }
        h0[(size_t)r * HROW + k]      = __floats2half2_rn(on.x, on.y);
        h0[(size_t)r * HROW + 32 + k] = __floats2half2_rn(tg.x, tg.y);
    }
}

// ---------------------------------------------------------------------------
// Fused SpMM (round-12 core, exact): persistent warps grid-striding; warp per
// row. Row w's edges live at [w*EDGE_CAP, w*EDGE_CAP + cursor[w]). 8 edges in
// flight (4 independent LDG.128/lane), pure HFMA2. Pad lanes carry ev=(0,0):
// v-half2=(0,0) keeps HFMA2 exact; pad gathers hit node 0 (L1-hot).
// shfl_xor(16)+HADD2 combine; lanes 0-15 store uint4.
// ---------------------------------------------------------------------------
__global__ void __launch_bounds__(256) spmm_fused_kernel(
    const int* __restrict__ cursor, const int2* __restrict__ edges,
    const __half2* __restrict__ xin, __half2* __restrict__ xout, int nrows)
{
    int lane = threadIdx.x & 31;
    int half = lane >> 4;
    int hl   = lane & 15;
    int wstep = (gridDim.x * 256) >> 5;
    const char* xbase = (const char*)xin;

    for (int w = (blockIdx.x * 256 + threadIdx.x) >> 5; w < nrows; w += wstep) {
        int start = w * EDGE_CAP;
        int end   = start + __ldg(&cursor[w]);

        __half2 acc0 = u_as_h2(0u), acc1 = u_as_h2(0u);
        __half2 acc2 = u_as_h2(0u), acc3 = u_as_h2(0u);

        for (int base = start; base < end; base += 32) {
            int2 ev = make_int2(0, 0);             // pad: col 0 / val (0,0)
            if (base + lane < end) ev = __ldcs(&edges[base + lane]);
            int cnt = min(32, end - base);
            for (int j = 0; j < cnt; j += 8) {
                int      cA = __shfl_sync(0xffffffffu, ev.x, j + half);
                unsigned vA = (unsigned)__shfl_sync(0xffffffffu, ev.y, j + half);
                int      cB = __shfl_sync(0xffffffffu, ev.x, j + 2 + half);
                unsigned vB = (unsigned)__shfl_sync(0xffffffffu, ev.y, j + 2 + half);
                int      cC = __shfl_sync(0xffffffffu, ev.x, j + 4 + half);
                unsigned vC = (unsigned)__shfl_sync(0xffffffffu, ev.y, j + 4 + half);
                int      cD = __shfl_sync(0xffffffffu, ev.x, j + 6 + half);
                unsigned vD = (unsigned)__shfl_sync(0xffffffffu, ev.y, j + 6 + half);

                uint4 rA = __ldg((const uint4*)(xbase + (size_t)cA * 256 + hl * 16));
                uint4 rB = __ldg((const uint4*)(xbase + (size_t)cB * 256 + hl * 16));
                uint4 rC = __ldg((const uint4*)(xbase + (size_t)cC * 256 + hl * 16));
                uint4 rD = __ldg((const uint4*)(xbase + (size_t)cD * 256 + hl * 16));

                __half2 vhA = u_as_h2(vA), vhB = u_as_h2(vB);
                __half2 vhC = u_as_h2(vC), vhD = u_as_h2(vD);

                acc0 = __hfma2(u_as_h2(rA.x), vhA, acc0);
                acc1 = __hfma2(u_as_h2(rA.y), vhA, acc1);
                acc2 = __hfma2(u_as_h2(rA.z), vhA, acc2);
                acc3 = __hfma2(u_as_h2(rA.w), vhA, acc3);

                acc0 = __hfma2(u_as_h2(rB.x), vhB, acc0);
                acc1 = __hfma2(u_as_h2(rB.y), vhB, acc1);
                acc2 = __hfma2(u_as_h2(rB.z), vhB, acc2);
                acc3 = __hfma2(u_as_h2(rB.w), vhB, acc3);

                acc0 = __hfma2(u_as_h2(rC.x), vhC, acc0);
                acc1 = __hfma2(u_as_h2(rC.y), vhC, acc1);
                acc2 = __hfma2(u_as_h2(rC.z), vhC, acc2);
                acc3 = __hfma2(u_as_h2(rC.w), vhC, acc3);

                acc0 = __hfma2(u_as_h2(rD.x), vhD, acc0);
                acc1 = __hfma2(u_as_h2(rD.y), vhD, acc1);
                acc2 = __hfma2(u_as_h2(rD.z), vhD, acc2);
                acc3 = __hfma2(u_as_h2(rD.w), vhD, acc3);
            }
        }

        acc0 = __hadd2(acc0, u_as_h2(__shfl_xor_sync(0xffffffffu, h2_as_u(acc0), 16)));
        acc1 = __hadd2(acc1, u_as_h2(__shfl_xor_sync(0xffffffffu, h2_as_u(acc1), 16)));
        acc2 = __hadd2(acc2, u_as_h2(__shfl_xor_sync(0xffffffffu, h2_as_u(acc2), 16)));
        acc3 = __hadd2(acc3, u_as_h2(__shfl_xor_sync(0xffffffffu, h2_as_u(acc3), 16)));

        if (lane < 16) {
            uint4 o;
            o.x = h2_as_u(acc0);
            o.y = h2_as_u(acc1);
            o.z = h2_as_u(acc2);
            o.w = h2_as_u(acc3);
            __stcs((uint4*)((char*)xout + (size_t)w * 256 + hl * 16), o);
        }
    }
}

// ---------------------------------------------------------------------------
// Layer-3 at sampled rows (both encodings), fp32 accumulation, fused with
// acc = 0.25*(ego_fp32 + X1 + X2 + X3). Online acc -> S, target acc -> out.
// (round-12 exact form: index-scaled addressing)
// ---------------------------------------------------------------------------
__global__ void __launch_bounds__(256) sampled_fused_kernel(
    const int* __restrict__ cursor, const int2* __restrict__ edges,
    const __half2* __restrict__ h1, const __half2* __restrict__ h2,
    const float2* __restrict__ ue_on, const float2* __restrict__ ie_on,
    const float2* __restrict__ ue_tg, const float2* __restrict__ ie_tg,
    const int* __restrict__ user_idx, const int* __restrict__ item_idx,
    float2* __restrict__ s_on,
    float2* __restrict__ out_utg, float2* __restrict__ out_itg,
    int b, int usplit)
{
    int s = (blockIdx.x * 256 + threadIdx.x) >> 5;
    if (s >= 2 * b) return;
    int lane = threadIdx.x & 31;
    int r = (s < b) ? __ldg(&user_idx[s]) : usplit + __ldg(&item_idx[s - b]);

    int start = r * EDGE_CAP;
    int end   = start + __ldg(&cursor[r]);
    float2 aon = make_float2(0.f, 0.f);
    float2 atg = make_float2(0.f, 0.f);
    for (int base = start; base < end; base += 32) {
        int2 ev = make_int2(0, 0);
        if (base + lane < end) ev = edges[base + lane];
        int cnt = min(32, end - base);
        for (int j = 0; j < cnt; j += 2) {
            int      cA = __shfl_sync(0xffffffffu, ev.x, j);
            unsigned uA = (unsigned)__shfl_sync(0xffffffffu, ev.y, j);
            int      cB = __shfl_sync(0xffffffffu, ev.x, j + 1);
            unsigned uB = (unsigned)__shfl_sync(0xffffffffu, ev.y, j + 1);
            float vA = __half2float(__low2half(u_as_h2(uA)));
            float vB = __half2float(__low2half(u_as_h2(uB)));
            const __half2* sA = h2 + (size_t)cA * HROW;
            const __half2* sB = h2 + (size_t)cB * HROW;
            float2 a  = __half22float2(__ldg(sA + lane));
            float2 t  = __half22float2(__ldg(sA + 32 + lane));
            float2 a2 = __half22float2(__ldg(sB + lane));
            float2 t2 = __half22float2(__ldg(sB + 32 + lane));
            aon.x = fmaf(vA, a.x, aon.x);
            aon.y = fmaf(vA, a.y, aon.y);
            atg.x = fmaf(vA, t.x, atg.x);
            atg.y = fmaf(vA, t.y, atg.y);
            aon.x = fmaf(vB, a2.x, aon.x);
            aon.y = fmaf(vB, a2.y, aon.y);
            atg.x = fmaf(vB, t2.x, atg.x);
            atg.y = fmaf(vB, t2.y, atg.y);
        }
    }

    float2 e_on = (r < usplit) ? __ldg(&ue_on[(size_t)r * 32 + lane])
                               : __ldg(&ie_on[(size_t)(r - usplit) * 32 + lane]);
    float2 e_tg = (r < usplit) ? __ldg(&ue_tg[(size_t)r * 32 + lane])
                               : __ldg(&ie_tg[(size_t)(r - usplit) * 32 + lane]);
    float2 x1on = __half22float2(__ldg(h1 + (size_t)r * HROW + lane));
    float2 x1tg = __half22float2(__ldg(h1 + (size_t)r * HROW + 32 + lane));
    float2 x2on = __half22float2(__ldg(h2 + (size_t)r * HROW + lane));
    float2 x2tg = __half22float2(__ldg(h2 + (size_t)r * HROW + 32 + lane));

    float2 ron, rtg;
    ron.x = 0.25f * (e_on.x + x1on.x + x2on.x + aon.x);
    ron.y = 0.25f * (e_on.y + x1on.y + x2on.y + aon.y);
    rtg.x = 0.25f * (e_tg.x + x1tg.x + x2tg.x + atg.x);
    rtg.y = 0.25f * (e_tg.y + x1tg.y + x2tg.y + atg.y);

    s_on[(size_t)s * 32 + lane] = ron;
    float2* dtg = (s < b) ? (out_utg + (size_t)s * 32 + lane)
                          : (out_itg + (size_t)(s - b) * 32 + lane);
    *dtg = rtg;
}

// ---------------------------------------------------------------------------
// Linear head (blocks [0,pb)) + cursor re-zero (blocks >= pb) for next call.
// ---------------------------------------------------------------------------
__global__ void __launch_bounds__(256) pred_zero_kernel(
    const float* __restrict__ S, const float* __restrict__ W,
    const float* __restrict__ bias,
    float* __restrict__ out_u, float* __restrict__ out_i, int b, int pb,
    int* __restrict__ cursor, int n)
{
    int tx = threadIdx.x, ty = threadIdx.y;
    int tid = ty * 64 + tx;

    if ((int)blockIdx.x >= pb) {               // cursor zeroing branch
        int i = (blockIdx.x - pb) * 256 + tid;
        if (i < n) cursor[i] = 0;
        return;
    }

    __shared__ float Wt[64][65];
    __shared__ float srow[4][64];
    __shared__ float sb[64];
    for (int idx = tid; idx < 4096; idx += 256)
        Wt[idx & 63][idx >> 6] = W[idx];
    if (tid < 64) sb[tid] = bias[tid];
    int s = blockIdx.x * 4 + ty;
    srow[ty][tx] = S[(size_t)s * 64 + tx];
    __syncthreads();

    float acc = sb[tx];
    #pragma unroll
    for (int k = 0; k < 64; k++)
        acc = fmaf(srow[ty][k], Wt[k][tx], acc);

    float* d = (s < b) ? (out_u + (size_t)s * 64 + tx)
                       : (out_i + (size_t)(s - b) * 64 + tx);
    *d = acc;
}

// ---------------------------------------------------------------------------
// Launch
// ---------------------------------------------------------------------------
extern "C" void kernel_launch(void* const* d_in, const int* in_sizes, int n_in,
                              void* d_out, int out_size) {
    const float* ue_on   = (const float*)d_in[0];
    const float* ie_on   = (const float*)d_in[1];
    const float* ue_tg   = (const float*)d_in[2];
    const float* ie_tg   = (const float*)d_in[3];
    const float* adj_val = (const float*)d_in[4];
    const float* pred_w  = (const float*)d_in[5];
    const float* pred_b  = (const float*)d_in[6];
    const int*   adj_row = (const int*)d_in[7];
    const int*   adj_col = (const int*)d_in[8];
    const int*   user_idx = (const int*)d_in[9];
    const int*   item_idx = (const int*)d_in[10];

    int uN  = in_sizes[0] / D;
    int iN  = in_sizes[1] / D;
    int n   = uN + iN;
    int nnz = in_sizes[4];
    int b   = in_sizes[9];

    int* cursor;
    int2* edges;
    __half2 *h0, *h1, *h2;
    float* S;
    cudaGetSymbolAddress((void**)&cursor, g_cursor);
    cudaGetSymbolAddress((void**)&edges,  g_edges);
    cudaGetSymbolAddress((void**)&h0,     g_H0);
    cudaGetSymbolAddress((void**)&h1,     g_H1);
    cudaGetSymbolAddress((void**)&h2,     g_H2);
    cudaGetSymbolAddress((void**)&S,      g_S);

    // --- bucket scatter + ego conversion (cursor pre-zeroed by prev call) ---
    int conv_blocks = (n * 32 + 255) / 256;
    scatter_convert_kernel<<<SCAT_BLOCKS + conv_blocks, 256>>>(
        adj_row, adj_col, adj_val, nnz, cursor, edges,
        (const float2*)ue_on, (const float2*)ie_on,
        (const float2*)ue_tg, (const float2*)ie_tg, h0, n, uN);

    int samp_blocks = (2 * b + 7) / 8;
    float* out = (float*)d_out;
    size_t BD = (size_t)b * D;

    spmm_fused_kernel<<<SPMM_BLOCKS, 256>>>(cursor, edges, h0, h1, n);
    spmm_fused_kernel<<<SPMM_BLOCKS, 256>>>(cursor, edges, h1, h2, n);
    sampled_fused_kernel<<<samp_blocks, 256>>>(cursor, edges, h1, h2,
        (const float2*)ue_on, (const float2*)ie_on,
        (const float2*)ue_tg, (const float2*)ie_tg,
        user_idx, item_idx,
        (float2*)S,
        (float2*)(out + BD),
        (float2*)(out + 3 * BD),
        b, uN);
    int pb = (2 * b) / 4;
    int zero_blocks = (n + 255) / 256;
    pred_zero_kernel<<<pb + zero_blocks, dim3(64, 4)>>>(S, pred_w, pred_b,
        out, out + 2 * BD, b, pb, cursor, n);
}

// round 17
// speedup vs baseline: 1.2541x; 1.1111x over previous
#include <cuda_runtime.h>
#include <cuda_fp16.h>

// ---------------------------------------------------------------------------
// BUIR / LightGCN forward, all-fp16 HFMA2 SpMM, bucketed CSR, sparse SpMM-2.
//   - Online+target embeddings interleaved per node: H[r] = [64 on | 64 tg]
//     fp16 = 256B row. One SpMM pass computes BOTH encodings' layers.
//   - Edges scattered into fixed 64-slot per-row buckets (no hist/scan).
//   - KEY CUT: X2 is only read at sampled rows and their neighbors (~46% of
//     rows). A mark pass (fused into SpMM-1's launch) flags needed rows; a
//     compact pass builds a worklist; SpMM-2 runs only over the worklist.
//     Unwritten X2 rows hold stale finite values that are only ever
//     multiplied by v=0 pad edges -> output unchanged and deterministic.
//   - SpMM: persistent warps, warp per row, 8 edges in flight, pure HFMA2.
//   - Layer 3 only at sampled rows (fp32 accum), fused acc=(ego+X1+X2+X3)/4.
// Output layout: [u_pred | u_target | i_pred | i_target], each [B,64] f32.
// ---------------------------------------------------------------------------

#define D        64
#define HROW     64          // half2 per node row (128 halfs = 256B)
#define N_NODES  300000
#define EDGE_CAP 64          // bucket capacity per row (max degree ~45)
#define B_MAX    4096
#define SCAT_BLOCKS 4096
#define SPMM_BLOCKS 1184     // 148 SMs * 8 resident CTAs

// Scratch (device globals — no allocation allowed in kernel_launch)
__device__ int           g_cursor[N_NODES];  // zero at load; re-zeroed each call
__device__ int2          g_edges[(size_t)N_NODES * EDGE_CAP];  // {col, half2(v,v)}
__device__ unsigned char g_need[N_NODES];    // zero at load; cleared by compact
__device__ int           g_work[N_NODES];
__device__ int           g_nwork;            // reset by scatter each call
__device__ __half2       g_H0[(size_t)N_NODES * HROW];
__device__ __half2       g_H1[(size_t)N_NODES * HROW];
__device__ __half2       g_H2[(size_t)N_NODES * HROW];
__device__ float         g_S[(size_t)2 * B_MAX * D];

static __device__ __forceinline__ unsigned h2_as_u(__half2 h) {
    return *reinterpret_cast<unsigned*>(&h);
}
static __device__ __forceinline__ __half2 u_as_h2(unsigned u) {
    return *reinterpret_cast<__half2*>(&u);
}

// ---------------------------------------------------------------------------
// Fused: bucket scatter (blocks [0,SCAT_BLOCKS)) + ego->fp16 convert (rest).
// Also resets the worklist counter for this call's compact.
// ---------------------------------------------------------------------------
__global__ void __launch_bounds__(256) scatter_convert_kernel(
    const int* __restrict__ row, const int* __restrict__ col,
    const float* __restrict__ val, int nnz,
    int* __restrict__ cursor, int2* __restrict__ edges,
    const float2* __restrict__ ue_on, const float2* __restrict__ ie_on,
    const float2* __restrict__ ue_tg, const float2* __restrict__ ie_tg,
    __half2* __restrict__ h0, int n, int usplit)
{
    if (blockIdx.x == 0 && threadIdx.x == 0) g_nwork = 0;
    if (blockIdx.x < SCAT_BLOCKS) {
        int n8 = nnz >> 3;                         // 8-edge chunks
        const int4*   row4 = (const int4*)row;
        const int4*   col4 = (const int4*)col;
        const float4* val4 = (const float4*)val;
        for (int i = blockIdx.x * 256 + threadIdx.x; i < n8;
             i += SCAT_BLOCKS * 256) {
            int4   r0 = __ldcs(&row4[2 * i]);
            int4   r1 = __ldcs(&row4[2 * i + 1]);
            int4   c0 = __ldcs(&col4[2 * i]);
            int4   c1 = __ldcs(&col4[2 * i + 1]);
            float4 v0 = __ldcs(&val4[2 * i]);
            float4 v1 = __ldcs(&val4[2 * i + 1]);
            int p0 = r0.x * EDGE_CAP + atomicAdd(&cursor[r0.x], 1);
            int p1 = r0.y * EDGE_CAP + atomicAdd(&cursor[r0.y], 1);
            int p2 = r0.z * EDGE_CAP + atomicAdd(&cursor[r0.z], 1);
            int p3 = r0.w * EDGE_CAP + atomicAdd(&cursor[r0.w], 1);
            int p4 = r1.x * EDGE_CAP + atomicAdd(&cursor[r1.x], 1);
            int p5 = r1.y * EDGE_CAP + atomicAdd(&cursor[r1.y], 1);
            int p6 = r1.z * EDGE_CAP + atomicAdd(&cursor[r1.z], 1);
            int p7 = r1.w * EDGE_CAP + atomicAdd(&cursor[r1.w], 1);
            __stcs(&edges[p0], make_int2(c0.x, (int)h2_as_u(__float2half2_rn(v0.x))));
            __stcs(&edges[p1], make_int2(c0.y, (int)h2_as_u(__float2half2_rn(v0.y))));
            __stcs(&edges[p2], make_int2(c0.z, (int)h2_as_u(__float2half2_rn(v0.z))));
            __stcs(&edges[p3], make_int2(c0.w, (int)h2_as_u(__float2half2_rn(v0.w))));
            __stcs(&edges[p4], make_int2(c1.x, (int)h2_as_u(__float2half2_rn(v1.x))));
            __stcs(&edges[p5], make_int2(c1.y, (int)h2_as_u(__float2half2_rn(v1.y))));
            __stcs(&edges[p6], make_int2(c1.z, (int)h2_as_u(__float2half2_rn(v1.z))));
            __stcs(&edges[p7], make_int2(c1.w, (int)h2_as_u(__float2half2_rn(v1.w))));
        }
        int t = (n8 << 3) + blockIdx.x * 256 + threadIdx.x;
        if (t < nnz) {
            int r = __ldcs(&row[t]);
            int pos = r * EDGE_CAP + atomicAdd(&cursor[r], 1);
            __stcs(&edges[pos],
                   make_int2(__ldcs(&col[t]),
                             (int)h2_as_u(__float2half2_rn(__ldcs(&val[t])))));
        }
    } else {
        int idx = (blockIdx.x - SCAT_BLOCKS) * 256 + threadIdx.x;
        if (idx >= n * 32) return;
        int r = idx >> 5;
        int k = idx & 31;
        float2 on, tg;
        if (r < usplit) {
            on = ue_on[(size_t)r * 32 + k];
            tg = ue_tg[(size_t)r * 32 + k];
        } else {
            on = ie_on[(size_t)(r - usplit) * 32 + k];
            tg = ie_tg[(size_t)(r - usplit) * 32 + k];
        }
        h0[(size_t)r * HROW + k]      = __floats2half2_rn(on.x, on.y);
        h0[(size_t)r * HROW + 32 + k] = __floats2half2_rn(tg.x, tg.y);
    }
}

// ---------------------------------------------------------------------------
// SpMM inner body (round-12 proven form), as a device function.
// ---------------------------------------------------------------------------
static __device__ __forceinline__ void spmm_row(
    int w, const int* __restrict__ cursor, const int2* __restrict__ edges,
    const char* __restrict__ xbase, __half2* __restrict__ xout,
    int lane, int half, int hl)
{
    int start = w * EDGE_CAP;
    int end   = start + __ldg(&cursor[w]);

    __half2 acc0 = u_as_h2(0u), acc1 = u_as_h2(0u);
    __half2 acc2 = u_as_h2(0u), acc3 = u_as_h2(0u);

    for (int base = start; base < end; base += 32) {
        int2 ev = make_int2(0, 0);             // pad: col 0 / val (0,0)
        if (base + lane < end) ev = __ldcs(&edges[base + lane]);
        int cnt = min(32, end - base);
        for (int j = 0; j < cnt; j += 8) {
            int      cA = __shfl_sync(0xffffffffu, ev.x, j + half);
            unsigned vA = (unsigned)__shfl_sync(0xffffffffu, ev.y, j + half);
            int      cB = __shfl_sync(0xffffffffu, ev.x, j + 2 + half);
            unsigned vB = (unsigned)__shfl_sync(0xffffffffu, ev.y, j + 2 + half);
            int      cC = __shfl_sync(0xffffffffu, ev.x, j + 4 + half);
            unsigned vC = (unsigned)__shfl_sync(0xffffffffu, ev.y, j + 4 + half);
            int      cD = __shfl_sync(0xffffffffu, ev.x, j + 6 + half);
            unsigned vD = (unsigned)__shfl_sync(0xffffffffu, ev.y, j + 6 + half);

            uint4 rA = __ldg((const uint4*)(xbase + (size_t)cA * 256 + hl * 16));
            uint4 rB = __ldg((const uint4*)(xbase + (size_t)cB * 256 + hl * 16));
            uint4 rC = __ldg((const uint4*)(xbase + (size_t)cC * 256 + hl * 16));
            uint4 rD = __ldg((const uint4*)(xbase + (size_t)cD * 256 + hl * 16));

            __half2 vhA = u_as_h2(vA), vhB = u_as_h2(vB);
            __half2 vhC = u_as_h2(vC), vhD = u_as_h2(vD);

            acc0 = __hfma2(u_as_h2(rA.x), vhA, acc0);
            acc1 = __hfma2(u_as_h2(rA.y), vhA, acc1);
            acc2 = __hfma2(u_as_h2(rA.z), vhA, acc2);
            acc3 = __hfma2(u_as_h2(rA.w), vhA, acc3);

            acc0 = __hfma2(u_as_h2(rB.x), vhB, acc0);
            acc1 = __hfma2(u_as_h2(rB.y), vhB, acc1);
            acc2 = __hfma2(u_as_h2(rB.z), vhB, acc2);
            acc3 = __hfma2(u_as_h2(rB.w), vhB, acc3);

            acc0 = __hfma2(u_as_h2(rC.x), vhC, acc0);
            acc1 = __hfma2(u_as_h2(rC.y), vhC, acc1);
            acc2 = __hfma2(u_as_h2(rC.z), vhC, acc2);
            acc3 = __hfma2(u_as_h2(rC.w), vhC, acc3);

            acc0 = __hfma2(u_as_h2(rD.x), vhD, acc0);
            acc1 = __hfma2(u_as_h2(rD.y), vhD, acc1);
            acc2 = __hfma2(u_as_h2(rD.z), vhD, acc2);
            acc3 = __hfma2(u_as_h2(rD.w), vhD, acc3);
        }
    }

    acc0 = __hadd2(acc0, u_as_h2(__shfl_xor_sync(0xffffffffu, h2_as_u(acc0), 16)));
    acc1 = __hadd2(acc1, u_as_h2(__shfl_xor_sync(0xffffffffu, h2_as_u(acc1), 16)));
    acc2 = __hadd2(acc2, u_as_h2(__shfl_xor_sync(0xffffffffu, h2_as_u(acc2), 16)));
    acc3 = __hadd2(acc3, u_as_h2(__shfl_xor_sync(0xffffffffu, h2_as_u(acc3), 16)));

    if (lane < 16) {
        uint4 o;
        o.x = h2_as_u(acc0);
        o.y = h2_as_u(acc1);
        o.z = h2_as_u(acc2);
        o.w = h2_as_u(acc3);
        __stcs((uint4*)((char*)xout + (size_t)w * 256 + hl * 16), o);
    }
}

// ---------------------------------------------------------------------------
// SpMM-1 (full, persistent) + fused MARK branch: blocks >= SPMM_BLOCKS flag
// the rows whose X2 will be read (sampled rows and their bucket columns).
// ---------------------------------------------------------------------------
__global__ void __launch_bounds__(256) spmm1_mark_kernel(
    const int* __restrict__ cursor, const int2* __restrict__ edges,
    const __half2* __restrict__ xin, __half2* __restrict__ xout, int nrows,
    const int* __restrict__ user_idx, const int* __restrict__ item_idx,
    unsigned char* __restrict__ need, int b, int usplit)
{
    if (blockIdx.x >= SPMM_BLOCKS) {
        // mark branch: warp per sampled row
        int s = ((blockIdx.x - SPMM_BLOCKS) * 256 + threadIdx.x) >> 5;
        if (s >= 2 * b) return;
        int lane = threadIdx.x & 31;
        int r = (s < b) ? __ldg(&user_idx[s]) : usplit + __ldg(&item_idx[s - b]);
        if (lane == 0) need[r] = 1;
        int deg = __ldg(&cursor[r]);
        int start = r * EDGE_CAP;
        for (int j = lane; j < deg; j += 32) {
            int c = __ldg(&edges[start + j]).x;
            need[c] = 1;
        }
        return;
    }

    int lane = threadIdx.x & 31;
    int half = lane >> 4;
    int hl   = lane & 15;
    int wstep = (SPMM_BLOCKS * 256) >> 5;
    const char* xbase = (const char*)xin;

    for (int w = (blockIdx.x * 256 + threadIdx.x) >> 5; w < nrows; w += wstep)
        spmm_row(w, cursor, edges, xbase, xout, lane, half, hl);
}

// ---------------------------------------------------------------------------
// Compact: flags -> worklist (order irrelevant); clears flags for next call.
// ---------------------------------------------------------------------------
__global__ void __launch_bounds__(256) compact_kernel(
    unsigned char* __restrict__ need, int n,
    int* __restrict__ work)
{
    int i = blockIdx.x * 256 + threadIdx.x;
    bool f = (i < n) && need[i];
    if (i < n) need[i] = 0;
    unsigned mask = __ballot_sync(0xffffffffu, f);
    int cnt = __popc(mask);
    int base = 0;
    if ((threadIdx.x & 31) == 0 && cnt)
        base = atomicAdd(&g_nwork, cnt);
    base = __shfl_sync(0xffffffffu, base, 0);
    if (f)
        work[base + __popc(mask & ((1u << (threadIdx.x & 31)) - 1u))] = i;
}

// ---------------------------------------------------------------------------
// SpMM-2 over the worklist (persistent).
// ---------------------------------------------------------------------------
__global__ void __launch_bounds__(256) spmm_wl_kernel(
    const int* __restrict__ cursor, const int2* __restrict__ edges,
    const __half2* __restrict__ xin, __half2* __restrict__ xout,
    const int* __restrict__ work)
{
    int nw = g_nwork;
    int lane = threadIdx.x & 31;
    int half = lane >> 4;
    int hl   = lane & 15;
    int wstep = (gridDim.x * 256) >> 5;
    const char* xbase = (const char*)xin;

    for (int idx = (blockIdx.x * 256 + threadIdx.x) >> 5; idx < nw; idx += wstep) {
        int w = __ldg(&work[idx]);
        spmm_row(w, cursor, edges, xbase, xout, lane, half, hl);
    }
}

// ---------------------------------------------------------------------------
// Layer-3 at sampled rows (both encodings), fp32 accumulation, fused with
// acc = 0.25*(ego_fp32 + X1 + X2 + X3). Online acc -> S, target acc -> out.
// ---------------------------------------------------------------------------
__global__ void __launch_bounds__(256) sampled_fused_kernel(
    const int* __restrict__ cursor, const int2* __restrict__ edges,
    const __half2* __restrict__ h1, const __half2* __restrict__ h2,
    const float2* __restrict__ ue_on, const float2* __restrict__ ie_on,
    const float2* __restrict__ ue_tg, const float2* __restrict__ ie_tg,
    const int* __restrict__ user_idx, const int* __restrict__ item_idx,
    float2* __restrict__ s_on,
    float2* __restrict__ out_utg, float2* __restrict__ out_itg,
    int b, int usplit)
{
    int s = (blockIdx.x * 256 + threadIdx.x) >> 5;
    if (s >= 2 * b) return;
    int lane = threadIdx.x & 31;
    int r = (s < b) ? __ldg(&user_idx[s]) : usplit + __ldg(&item_idx[s - b]);

    int start = r * EDGE_CAP;
    int end   = start + __ldg(&cursor[r]);
    float2 aon = make_float2(0.f, 0.f);
    float2 atg = make_float2(0.f, 0.f);
    for (int base = start; base < end; base += 32) {
        int2 ev = make_int2(0, 0);
        if (base + lane < end) ev = edges[base + lane];
        int cnt = min(32, end - base);
        for (int j = 0; j < cnt; j += 2) {
            int      cA = __shfl_sync(0xffffffffu, ev.x, j);
            unsigned uA = (unsigned)__shfl_sync(0xffffffffu, ev.y, j);
            int      cB = __shfl_sync(0xffffffffu, ev.x, j + 1);
            unsigned uB = (unsigned)__shfl_sync(0xffffffffu, ev.y, j + 1);
            float vA = __half2float(__low2half(u_as_h2(uA)));
            float vB = __half2float(__low2half(u_as_h2(uB)));
            const __half2* sA = h2 + (size_t)cA * HROW;
            const __half2* sB = h2 + (size_t)cB * HROW;
            float2 a  = __half22float2(__ldg(sA + lane));
            float2 t  = __half22float2(__ldg(sA + 32 + lane));
            float2 a2 = __half22float2(__ldg(sB + lane));
            float2 t2 = __half22float2(__ldg(sB + 32 + lane));
            aon.x = fmaf(vA, a.x, aon.x);
            aon.y = fmaf(vA, a.y, aon.y);
            atg.x = fmaf(vA, t.x, atg.x);
            atg.y = fmaf(vA, t.y, atg.y);
            aon.x = fmaf(vB, a2.x, aon.x);
            aon.y = fmaf(vB, a2.y, aon.y);
            atg.x = fmaf(vB, t2.x, atg.x);
            atg.y = fmaf(vB, t2.y, atg.y);
        }
    }

    float2 e_on = (r < usplit) ? __ldg(&ue_on[(size_t)r * 32 + lane])
                               : __ldg(&ie_on[(size_t)(r - usplit) * 32 + lane]);
    float2 e_tg = (r < usplit) ? __ldg(&ue_tg[(size_t)r * 32 + lane])
                               : __ldg(&ie_tg[(size_t)(r - usplit) * 32 + lane]);
    float2 x1on = __half22float2(__ldg(h1 + (size_t)r * HROW + lane));
    float2 x1tg = __half22float2(__ldg(h1 + (size_t)r * HROW + 32 + lane));
    float2 x2on = __half22float2(__ldg(h2 + (size_t)r * HROW + lane));
    float2 x2tg = __half22float2(__ldg(h2 + (size_t)r * HROW + 32 + lane));

    float2 ron, rtg;
    ron.x = 0.25f * (e_on.x + x1on.x + x2on.x + aon.x);
    ron.y = 0.25f * (e_on.y + x1on.y + x2on.y + aon.y);
    rtg.x = 0.25f * (e_tg.x + x1tg.x + x2tg.x + atg.x);
    rtg.y = 0.25f * (e_tg.y + x1tg.y + x2tg.y + atg.y);

    s_on[(size_t)s * 32 + lane] = ron;
    float2* dtg = (s < b) ? (out_utg + (size_t)s * 32 + lane)
                          : (out_itg + (size_t)(s - b) * 32 + lane);
    *dtg = rtg;
}

// ---------------------------------------------------------------------------
// Linear head (blocks [0,pb)) + cursor re-zero (blocks >= pb) for next call.
// ---------------------------------------------------------------------------
__global__ void __launch_bounds__(256) pred_zero_kernel(
    const float* __restrict__ S, const float* __restrict__ W,
    const float* __restrict__ bias,
    float* __restrict__ out_u, float* __restrict__ out_i, int b, int pb,
    int* __restrict__ cursor, int n)
{
    int tx = threadIdx.x, ty = threadIdx.y;
    int tid = ty * 64 + tx;

    if ((int)blockIdx.x >= pb) {               // cursor zeroing branch
        int i = (blockIdx.x - pb) * 256 + tid;
        if (i < n) cursor[i] = 0;
        return;
    }

    __shared__ float Wt[64][65];
    __shared__ float srow[4][64];
    __shared__ float sb[64];
    for (int idx = tid; idx < 4096; idx += 256)
        Wt[idx & 63][idx >> 6] = W[idx];
    if (tid < 64) sb[tid] = bias[tid];
    int s = blockIdx.x * 4 + ty;
    srow[ty][tx] = S[(size_t)s * 64 + tx];
    __syncthreads();

    float acc = sb[tx];
    #pragma unroll
    for (int k = 0; k < 64; k++)
        acc = fmaf(srow[ty][k], Wt[k][tx], acc);

    float* d = (s < b) ? (out_u + (size_t)s * 64 + tx)
                       : (out_i + (size_t)(s - b) * 64 + tx);
    *d = acc;
}

// ---------------------------------------------------------------------------
// Launch
// ---------------------------------------------------------------------------
extern "C" void kernel_launch(void* const* d_in, const int* in_sizes, int n_in,
                              void* d_out, int out_size) {
    const float* ue_on   = (const float*)d_in[0];
    const float* ie_on   = (const float*)d_in[1];
    const float* ue_tg   = (const float*)d_in[2];
    const float* ie_tg   = (const float*)d_in[3];
    const float* adj_val = (const float*)d_in[4];
    const float* pred_w  = (const float*)d_in[5];
    const float* pred_b  = (const float*)d_in[6];
    const int*   adj_row = (const int*)d_in[7];
    const int*   adj_col = (const int*)d_in[8];
    const int*   user_idx = (const int*)d_in[9];
    const int*   item_idx = (const int*)d_in[10];

    int uN  = in_sizes[0] / D;
    int iN  = in_sizes[1] / D;
    int n   = uN + iN;
    int nnz = in_sizes[4];
    int b   = in_sizes[9];

    int *cursor, *work;
    unsigned char* need;
    int2* edges;
    __half2 *h0, *h1, *h2;
    float* S;
    cudaGetSymbolAddress((void**)&cursor, g_cursor);
    cudaGetSymbolAddress((void**)&work,   g_work);
    cudaGetSymbolAddress((void**)&need,   g_need);
    cudaGetSymbolAddress((void**)&edges,  g_edges);
    cudaGetSymbolAddress((void**)&h0,     g_H0);
    cudaGetSymbolAddress((void**)&h1,     g_H1);
    cudaGetSymbolAddress((void**)&h2,     g_H2);
    cudaGetSymbolAddress((void**)&S,      g_S);

    // --- bucket scatter + ego conversion (cursor pre-zeroed by prev call) ---
    int conv_blocks = (n * 32 + 255) / 256;
    scatter_convert_kernel<<<SCAT_BLOCKS + conv_blocks, 256>>>(
        adj_row, adj_col, adj_val, nnz, cursor, edges,
        (const float2*)ue_on, (const float2*)ie_on,
        (const float2*)ue_tg, (const float2*)ie_tg, h0, n, uN);

    int samp_blocks = (2 * b + 7) / 8;
    float* out = (float*)d_out;
    size_t BD = (size_t)b * D;

    // SpMM-1 (full) with fused mark of needed-X2 rows
    spmm1_mark_kernel<<<SPMM_BLOCKS + samp_blocks, 256>>>(
        cursor, edges, h0, h1, n, user_idx, item_idx, need, b, uN);
    // flags -> worklist (also clears flags)
    compact_kernel<<<(n + 255) / 256, 256>>>(need, n, work);
    // SpMM-2 only over needed rows
    spmm_wl_kernel<<<SPMM_BLOCKS, 256>>>(cursor, edges, h1, h2, work);

    sampled_fused_kernel<<<samp_blocks, 256>>>(cursor, edges, h1, h2,
        (const float2*)ue_on, (const float2*)ie_on,
        (const float2*)ue_tg, (const float2*)ie_tg,
        user_idx, item_idx,
        (float2*)S,
        (float2*)(out + BD),
        (float2*)(out + 3 * BD),
        b, uN);
    int pb = (2 * b) / 4;
    int zero_blocks = (n + 255) / 256;
    pred_zero_kernel<<<pb + zero_blocks, dim3(64, 4)>>>(S, pred_w, pred_b,
        out, out + 2 * BD, b, pb, cursor, n);
}